// round 4
// baseline (speedup 1.0000x reference)
#include <cuda_runtime.h>
#include <cuda_bf16.h>
#include <cstdint>

// ============================================================
// ContrastiveLoss: loss = mean_i [ lse_i - l_ii ],
//   l_ij = (e_i . e_j)/T on L2-normalized rows, T = 0.07
// sm_103 family-target-safe path: mma.sync (HMMA) + ldmatrix +
// cp.async (tcgen05 is sm_103a-only PTX and the harness builds
// through compute_103, so it cannot be used).
// ============================================================

#define TEMP 0.07f
static constexpr int NROWS = 16384;
static constexpr int NDIM  = 256;
static constexpr int MT    = 128;            // rows per CTA
static constexpr int NTILE = 128;            // cols per column-tile
static constexpr int NT    = NROWS / NTILE;  // 128 column tiles
static constexpr int NCTA  = NROWS / MT;     // 128 CTAs

// SMEM layout (dynamic): A 64KB | B double buffer 2x64KB | stash
static constexpr int SM_A     = 0;
static constexpr int SM_B     = 65536;
static constexpr int SM_STASH = 65536 + 2 * 65536;     // 196608
static constexpr int SMEM_TOTAL = SM_STASH + 2048 + 64;  // ~198.7 KB

__device__ __align__(1024) __nv_bfloat16 g_norm[NROWS * NDIM];
__device__ float g_diag[NROWS];
__device__ float g_partial[NCTA];

// ---------------- helpers ----------------
__device__ __forceinline__ uint32_t smem_u32(const void* p) {
    uint32_t a;
    asm("{ .reg .u64 t; cvta.to.shared.u64 t, %1; cvt.u32.u64 %0, t; }"
        : "=r"(a) : "l"(p));
    return a;
}

__device__ __forceinline__ void cp_async16(uint32_t s, const void* g) {
    asm volatile("cp.async.cg.shared.global [%0], [%1], 16;"
                 :: "r"(s), "l"(g) : "memory");
}
#define CP_COMMIT() asm volatile("cp.async.commit_group;" ::: "memory")
#define CP_WAIT(n)  asm volatile("cp.async.wait_group %0;" :: "n"(n) : "memory")

__device__ __forceinline__ void ldsm4(uint32_t& r0, uint32_t& r1,
                                      uint32_t& r2, uint32_t& r3, uint32_t a) {
    asm volatile("ldmatrix.sync.aligned.m8n8.x4.shared.b16 {%0,%1,%2,%3}, [%4];"
                 : "=r"(r0), "=r"(r1), "=r"(r2), "=r"(r3) : "r"(a));
}

__device__ __forceinline__ void mma16816(float* c, const uint32_t* a, const uint32_t* b) {
    asm volatile(
        "mma.sync.aligned.m16n8k16.row.col.f32.bf16.bf16.f32 "
        "{%0,%1,%2,%3}, {%4,%5,%6,%7}, {%8,%9}, {%0,%1,%2,%3};"
        : "+f"(c[0]), "+f"(c[1]), "+f"(c[2]), "+f"(c[3])
        : "r"(a[0]), "r"(a[1]), "r"(a[2]), "r"(a[3]), "r"(b[0]), "r"(b[1]));
}

__device__ __forceinline__ float ex2f(float x) {
    float y;
    asm("ex2.approx.ftz.f32 %0, %1;" : "=f"(y) : "f"(x));
    return y;
}

// ---------------- Kernel 1: L2 normalize fp32 -> bf16, + bf16 self-dot ----------------
__global__ void __launch_bounds__(256) normalize_kernel(const float* __restrict__ emb) {
    const int row  = blockIdx.x * 8 + (threadIdx.x >> 5);
    const int lane = threadIdx.x & 31;
    const float4* p = reinterpret_cast<const float4*>(emb + (size_t)row * NDIM);
    float4 x0 = p[2 * lane];
    float4 x1 = p[2 * lane + 1];
    float ss = x0.x * x0.x + x0.y * x0.y + x0.z * x0.z + x0.w * x0.w
             + x1.x * x1.x + x1.y * x1.y + x1.z * x1.z + x1.w * x1.w;
    #pragma unroll
    for (int o = 16; o; o >>= 1) ss += __shfl_xor_sync(0xffffffffu, ss, o);
    const float s = 1.0f / fmaxf(sqrtf(ss), 1e-12f);

    __nv_bfloat162 h0 = __floats2bfloat162_rn(x0.x * s, x0.y * s);
    __nv_bfloat162 h1 = __floats2bfloat162_rn(x0.z * s, x0.w * s);
    __nv_bfloat162 h2 = __floats2bfloat162_rn(x1.x * s, x1.y * s);
    __nv_bfloat162 h3 = __floats2bfloat162_rn(x1.z * s, x1.w * s);
    __nv_bfloat162* dst = reinterpret_cast<__nv_bfloat162*>(g_norm + (size_t)row * NDIM);
    dst[4 * lane + 0] = h0;
    dst[4 * lane + 1] = h1;
    dst[4 * lane + 2] = h2;
    dst[4 * lane + 3] = h3;

    float d0 = __bfloat162float(h0.x), d1 = __bfloat162float(h0.y);
    float d2 = __bfloat162float(h1.x), d3 = __bfloat162float(h1.y);
    float d4 = __bfloat162float(h2.x), d5 = __bfloat162float(h2.y);
    float d6 = __bfloat162float(h3.x), d7 = __bfloat162float(h3.y);
    float dd = d0 * d0 + d1 * d1 + d2 * d2 + d3 * d3
             + d4 * d4 + d5 * d5 + d6 * d6 + d7 * d7;
    #pragma unroll
    for (int o = 16; o; o >>= 1) dd += __shfl_xor_sync(0xffffffffu, dd, o);
    if (lane == 0) g_diag[row] = dd;
}

// ---------------- Kernel 2: main HMMA GEMM + fused exp/rowsum ----------------
// Smem tile layout (A and B identical): row r (0..127) of 256 bf16 = 32
// 16B chunks; chunk c stored at r*512 + (c ^ (r&7))*16  -> ldmatrix
// conflict-free (8 rows of a matrix hit 8 distinct bank groups).
__global__ void __launch_bounds__(256, 1) contrastive_main() {
    extern __shared__ char smem[];
    const uint32_t sb = smem_u32(smem);
    const int tid  = threadIdx.x;
    const int wid  = tid >> 5;
    const int lane = tid & 31;
    const int m0   = blockIdx.x * MT;

    const int warp_m = (wid >> 2) * 64;  // 0 or 64
    const int warp_n = (wid & 3) * 32;   // 0,32,64,96

    // ---- prologue: A tile + B tile 0 (group 0), B tile 1 (group 1) ----
    {
        const char* gA = reinterpret_cast<const char*>(g_norm) + (size_t)m0 * 512;
        #pragma unroll 4
        for (int i = tid; i < 4096; i += 256) {
            int row = i >> 5, c = i & 31;
            cp_async16(sb + SM_A + row * 512 + (uint32_t)((c ^ (row & 7)) << 4),
                       gA + (size_t)i * 16);
        }
        const char* gB = reinterpret_cast<const char*>(g_norm);
        #pragma unroll 4
        for (int i = tid; i < 4096; i += 256) {
            int row = i >> 5, c = i & 31;
            cp_async16(sb + SM_B + row * 512 + (uint32_t)((c ^ (row & 7)) << 4),
                       gB + (size_t)i * 16);
        }
    }
    CP_COMMIT();
    {
        const char* gB = reinterpret_cast<const char*>(g_norm) + 65536;
        #pragma unroll 4
        for (int i = tid; i < 4096; i += 256) {
            int row = i >> 5, c = i & 31;
            cp_async16(sb + SM_B + 65536 + row * 512 + (uint32_t)((c ^ (row & 7)) << 4),
                       gB + (size_t)i * 16);
        }
    }
    CP_COMMIT();

    // ---- per-lane ldmatrix base addresses ----
    // A x4 (m16k16): matrix_id = lane>>3; row = warp_m + mt*16 + (mid&1)*8 + (lane&7),
    //                chunk = 2*ks + (mid>>1)
    // B x4 (two n8k16): row = warp_n + np*16 + (mid>>1)*8 + (lane&7),
    //                chunk = 2*ks + (mid&1)
    const int rlo = lane & 7;
    uint32_t baseA[4];
    #pragma unroll
    for (int mt = 0; mt < 4; mt++)
        baseA[mt] = sb + SM_A +
                    (uint32_t)(warp_m + mt * 16 + ((lane >> 3) & 1) * 8 + rlo) * 512u;
    uint32_t rowB[2];
    #pragma unroll
    for (int np = 0; np < 2; np++)
        rowB[np] = (uint32_t)(warp_n + np * 16 + ((lane >> 4) & 1) * 8 + rlo) * 512u;
    const uint32_t aSel = (uint32_t)(lane >> 4);        // chunk add for A
    const uint32_t bSel = (uint32_t)((lane >> 3) & 1);  // chunk add for B

    const float K2L = 20.60992915555662f;  // log2(e)/T : exp((s-1)/T) = 2^(s*K2L - K2L)
    float rs[8];
    #pragma unroll
    for (int i = 0; i < 8; i++) rs[i] = 0.0f;

    // ---- main loop over 128 column tiles ----
    for (int t = 0; t < NT; t++) {
        if (t + 1 < NT) { CP_WAIT(1); } else { CP_WAIT(0); }
        __syncthreads();

        const uint32_t bbase = sb + SM_B + (uint32_t)(t & 1) * 65536u;

        float c[4][4][4];
        #pragma unroll
        for (int mt = 0; mt < 4; mt++)
            #pragma unroll
            for (int nt = 0; nt < 4; nt++)
                #pragma unroll
                for (int k = 0; k < 4; k++) c[mt][nt][k] = 0.0f;

        #pragma unroll 4
        for (int ks = 0; ks < 16; ks++) {
            const uint32_t swA = (uint32_t)(((2u * ks + aSel) ^ (uint32_t)rlo) << 4);
            const uint32_t swB = (uint32_t)(((2u * ks + bSel) ^ (uint32_t)rlo) << 4);

            uint32_t a[4][4];
            #pragma unroll
            for (int mt = 0; mt < 4; mt++)
                ldsm4(a[mt][0], a[mt][1], a[mt][2], a[mt][3], baseA[mt] + swA);

            uint32_t b[4][2];
            ldsm4(b[0][0], b[0][1], b[1][0], b[1][1], bbase + rowB[0] + swB);
            ldsm4(b[2][0], b[2][1], b[3][0], b[3][1], bbase + rowB[1] + swB);

            #pragma unroll
            for (int mt = 0; mt < 4; mt++)
                #pragma unroll
                for (int nt = 0; nt < 4; nt++)
                    mma16816(c[mt][nt], a[mt], b[nt]);
        }
        __syncthreads();  // all warps done reading buf (t&1) before overwrite

        if (t + 2 < NT) {
            const char* gB = reinterpret_cast<const char*>(g_norm) + (size_t)(t + 2) * 65536;
            const uint32_t nb = sb + SM_B + (uint32_t)(t & 1) * 65536u;
            #pragma unroll 4
            for (int i = tid; i < 4096; i += 256) {
                int row = i >> 5, cc = i & 31;
                cp_async16(nb + row * 512 + (uint32_t)((cc ^ (row & 7)) << 4),
                           gB + (size_t)i * 16);
            }
            CP_COMMIT();
        }

        // fused epilogue: exp((s-1)/T) accumulated into per-row sums
        // c-frag: c0,c1 -> row gid (rows warp_m+mt*16+(lane>>2)); c2,c3 -> +8
        #pragma unroll
        for (int mt = 0; mt < 4; mt++) {
            float lo = 0.0f, hi = 0.0f;
            #pragma unroll
            for (int nt = 0; nt < 4; nt++) {
                lo += ex2f(fmaf(c[mt][nt][0], K2L, -K2L));
                lo += ex2f(fmaf(c[mt][nt][1], K2L, -K2L));
                hi += ex2f(fmaf(c[mt][nt][2], K2L, -K2L));
                hi += ex2f(fmaf(c[mt][nt][3], K2L, -K2L));
            }
            rs[mt * 2 + 0] += lo;
            rs[mt * 2 + 1] += hi;
        }
    }

    // ---- reduce row sums ----
    #pragma unroll
    for (int i = 0; i < 8; i++) {
        float v = rs[i];
        v += __shfl_xor_sync(0xffffffffu, v, 1);
        v += __shfl_xor_sync(0xffffffffu, v, 2);
        rs[i] = v;
    }
    float* stash = reinterpret_cast<float*>(smem + SM_STASH);
    if ((lane & 3) == 0) {
        #pragma unroll
        for (int mt = 0; mt < 4; mt++)
            #pragma unroll
            for (int h = 0; h < 2; h++) {
                int row = warp_m + mt * 16 + h * 8 + (lane >> 2);
                stash[(wid & 3) * 128 + row] = rs[mt * 2 + h];
            }
    }
    __syncthreads();

    if (wid < 4) {
        const int row = wid * 32 + lane;
        float tot = stash[row] + stash[128 + row] + stash[256 + row] + stash[384 + row];
        float loss = logf(tot) + (1.0f - g_diag[m0 + row]) * (1.0f / TEMP);
        #pragma unroll
        for (int o = 16; o; o >>= 1) loss += __shfl_xor_sync(0xffffffffu, loss, o);
        if (lane == 0) reinterpret_cast<float*>(smem + SM_STASH + 2048)[wid] = loss;
    }
    __syncthreads();
    if (tid == 0) {
        float* p = reinterpret_cast<float*>(smem + SM_STASH + 2048);
        g_partial[blockIdx.x] = (p[0] + p[1]) + (p[2] + p[3]);
    }
}

// ---------------- Kernel 3: deterministic final reduce ----------------
__global__ void __launch_bounds__(128) finalize_kernel(float* out) {
    const int tid = threadIdx.x;
    float v = g_partial[tid];
    #pragma unroll
    for (int o = 16; o; o >>= 1) v += __shfl_xor_sync(0xffffffffu, v, o);
    __shared__ float s4[4];
    if ((tid & 31) == 0) s4[tid >> 5] = v;
    __syncthreads();
    if (tid == 0) out[0] = ((s4[0] + s4[1]) + (s4[2] + s4[3])) * (1.0f / (float)NROWS);
}

// ---------------- launch ----------------
extern "C" void kernel_launch(void* const* d_in, const int* in_sizes, int n_in,
                              void* d_out, int out_size) {
    const float* emb = (const float*)d_in[0];
    float* out = (float*)d_out;
    (void)in_sizes; (void)n_in; (void)out_size;

    cudaFuncSetAttribute(contrastive_main,
                         cudaFuncAttributeMaxDynamicSharedMemorySize, SMEM_TOTAL);

    normalize_kernel<<<NROWS / 8, 256>>>(emb);
    contrastive_main<<<NCTA, 256, SMEM_TOTAL>>>();
    finalize_kernel<<<1, 128>>>(out);
}

// round 7
// speedup vs baseline: 1.8201x; 1.8201x over previous
#include <cuda_runtime.h>
#include <cuda_bf16.h>
#include <cstdint>

// ============================================================
// ContrastiveLoss: loss = mean_i [ lse_i - l_ii ],
//   l_ij = (e_i . e_j)/T on L2-normalized rows, T = 0.07
// mma.sync (HMMA) path (tcgen05 PTX rejected by compute_103
// family target). Round 5: exploit Gram-matrix symmetry —
// compute only the 8256 unordered block pairs (halves HMMA and
// exp work); each tile yields rowsums (block a) AND colsums
// (block b, written to deterministic per-slot global buffer).
// ============================================================

#define TEMP 0.07f
static constexpr int NROWS = 16384;
static constexpr int NDIM  = 256;
static constexpr int MT    = 128;            // rows per block
static constexpr int NB    = NROWS / MT;     // 128 blocks
static constexpr int NCTA  = NB;             // 1 CTA per row-block

// SMEM layout (dynamic): A 64KB | B double buffer 2x64KB | stashes
static constexpr int SM_A      = 0;
static constexpr int SM_B      = 65536;
static constexpr int SM_CSTASH = 65536 + 2 * 65536;          // 196608: 2x128 floats
static constexpr int SM_RSTASH = SM_CSTASH + 1024;           // 512 floats
static constexpr int SM_FIN    = SM_RSTASH + 2048;           // 4 floats
static constexpr int SMEM_TOTAL = SM_FIN + 64;

__device__ __align__(1024) __nv_bfloat16 g_norm[NROWS * NDIM];
__device__ float g_diag[NROWS];
__device__ float g_rs[NROWS];                 // CTA-local rowsums (unique writer)
__device__ float g_cs[NB * 64 * MT];          // colsum slots [b][slot][row], 4MB
__device__ float g_partial[NB];

// ---------------- helpers ----------------
__device__ __forceinline__ uint32_t smem_u32(const void* p) {
    uint32_t a;
    asm("{ .reg .u64 t; cvta.to.shared.u64 t, %1; cvt.u32.u64 %0, t; }"
        : "=r"(a) : "l"(p));
    return a;
}

__device__ __forceinline__ void cp_async16(uint32_t s, const void* g) {
    asm volatile("cp.async.cg.shared.global [%0], [%1], 16;"
                 :: "r"(s), "l"(g) : "memory");
}
#define CP_COMMIT() asm volatile("cp.async.commit_group;" ::: "memory")
#define CP_WAIT(n)  asm volatile("cp.async.wait_group %0;" :: "n"(n) : "memory")

__device__ __forceinline__ void ldsm4(uint32_t& r0, uint32_t& r1,
                                      uint32_t& r2, uint32_t& r3, uint32_t a) {
    asm volatile("ldmatrix.sync.aligned.m8n8.x4.shared.b16 {%0,%1,%2,%3}, [%4];"
                 : "=r"(r0), "=r"(r1), "=r"(r2), "=r"(r3) : "r"(a));
}

__device__ __forceinline__ void mma16816(float* c, const uint32_t* a, const uint32_t* b) {
    asm volatile(
        "mma.sync.aligned.m16n8k16.row.col.f32.bf16.bf16.f32 "
        "{%0,%1,%2,%3}, {%4,%5,%6,%7}, {%8,%9}, {%0,%1,%2,%3};"
        : "+f"(c[0]), "+f"(c[1]), "+f"(c[2]), "+f"(c[3])
        : "r"(a[0]), "r"(a[1]), "r"(a[2]), "r"(a[3]), "r"(b[0]), "r"(b[1]));
}

__device__ __forceinline__ float ex2f(float x) {
    float y;
    asm("ex2.approx.ftz.f32 %0, %1;" : "=f"(y) : "f"(x));
    return y;
}

// load one 128x256-bf16 block into swizzled smem tile (all 256 threads)
__device__ __forceinline__ void load_tile_async(uint32_t dst, const char* src, int tid) {
    #pragma unroll 4
    for (int i = tid; i < 4096; i += 256) {
        int row = i >> 5, c = i & 31;
        cp_async16(dst + row * 512 + (uint32_t)((c ^ (row & 7)) << 4),
                   src + (size_t)i * 16);
    }
}

// ---------------- Kernel 1: L2 normalize fp32 -> bf16, + bf16 self-dot ----------------
__global__ void __launch_bounds__(256) normalize_kernel(const float* __restrict__ emb) {
    const int row  = blockIdx.x * 8 + (threadIdx.x >> 5);
    const int lane = threadIdx.x & 31;
    const float4* p = reinterpret_cast<const float4*>(emb + (size_t)row * NDIM);
    float4 x0 = p[2 * lane];
    float4 x1 = p[2 * lane + 1];
    float ss = x0.x * x0.x + x0.y * x0.y + x0.z * x0.z + x0.w * x0.w
             + x1.x * x1.x + x1.y * x1.y + x1.z * x1.z + x1.w * x1.w;
    #pragma unroll
    for (int o = 16; o; o >>= 1) ss += __shfl_xor_sync(0xffffffffu, ss, o);
    const float s = 1.0f / fmaxf(sqrtf(ss), 1e-12f);

    __nv_bfloat162 h0 = __floats2bfloat162_rn(x0.x * s, x0.y * s);
    __nv_bfloat162 h1 = __floats2bfloat162_rn(x0.z * s, x0.w * s);
    __nv_bfloat162 h2 = __floats2bfloat162_rn(x1.x * s, x1.y * s);
    __nv_bfloat162 h3 = __floats2bfloat162_rn(x1.z * s, x1.w * s);
    __nv_bfloat162* dst = reinterpret_cast<__nv_bfloat162*>(g_norm + (size_t)row * NDIM);
    dst[4 * lane + 0] = h0;
    dst[4 * lane + 1] = h1;
    dst[4 * lane + 2] = h2;
    dst[4 * lane + 3] = h3;

    float d0 = __bfloat162float(h0.x), d1 = __bfloat162float(h0.y);
    float d2 = __bfloat162float(h1.x), d3 = __bfloat162float(h1.y);
    float d4 = __bfloat162float(h2.x), d5 = __bfloat162float(h2.y);
    float d6 = __bfloat162float(h3.x), d7 = __bfloat162float(h3.y);
    float dd = d0 * d0 + d1 * d1 + d2 * d2 + d3 * d3
             + d4 * d4 + d5 * d5 + d6 * d6 + d7 * d7;
    #pragma unroll
    for (int o = 16; o; o >>= 1) dd += __shfl_xor_sync(0xffffffffu, dd, o);
    if (lane == 0) g_diag[row] = dd;
}

// ---------------- Kernel 2: symmetric HMMA GEMM + fused exp/row+col sums ----------------
// CTA a owns: diagonal tile (t=0) + tiles b=(a+t)&127 for t=1..J,
// J = 64 if a<64 else 63 (balanced round-robin over unordered pairs).
__global__ void __launch_bounds__(256, 1) contrastive_main() {
    extern __shared__ char smem[];
    const uint32_t sb = smem_u32(smem);
    const int tid  = threadIdx.x;
    const int wid  = tid >> 5;
    const int lane = tid & 31;
    const int a    = blockIdx.x;
    const int m0   = a * MT;
    const int J    = (a < 64) ? 64 : 63;

    const int warp_m = (wid >> 2) * 64;  // 0 or 64
    const int warp_n = (wid & 3) * 32;   // 0,32,64,96

    // ---- prologue: A (resident) + B(t=1) as group 1; B(t=2) as group 2 ----
    const char* gbase = reinterpret_cast<const char*>(g_norm);
    load_tile_async(sb + SM_A, gbase + (size_t)a * 65536, tid);
    load_tile_async(sb + SM_B + 65536, gbase + (size_t)(((a + 1) & 127)) * 65536, tid);
    CP_COMMIT();
    load_tile_async(sb + SM_B, gbase + (size_t)(((a + 2) & 127)) * 65536, tid);
    CP_COMMIT();

    // ---- per-lane ldmatrix base addresses ----
    const int rlo = lane & 7;
    uint32_t baseA[4];
    #pragma unroll
    for (int mt = 0; mt < 4; mt++)
        baseA[mt] = sb + SM_A +
                    (uint32_t)(warp_m + mt * 16 + ((lane >> 3) & 1) * 8 + rlo) * 512u;
    uint32_t rowB[2];
    #pragma unroll
    for (int np = 0; np < 2; np++)
        rowB[np] = (uint32_t)(warp_n + np * 16 + ((lane >> 4) & 1) * 8 + rlo) * 512u;
    const uint32_t aSel = (uint32_t)(lane >> 4);
    const uint32_t bSel = (uint32_t)((lane >> 3) & 1);

    const float K2L = 20.60992915555662f;  // log2(e)/T : exp((s-1)/T) = 2^(s*K2L - K2L)
    float rs[8];
    #pragma unroll
    for (int i = 0; i < 8; i++) rs[i] = 0.0f;

    float* stashC0 = reinterpret_cast<float*>(smem + SM_CSTASH);
    float* stashC1 = stashC0 + 128;

    // ---- loop over owned tiles; t=0 is the diagonal (B = resident A) ----
    for (int t = 0; t <= J; t++) {
        CP_WAIT(1);
        __syncthreads();

        const uint32_t bbase = (t == 0) ? (sb + SM_A)
                                        : (sb + SM_B + (uint32_t)(t & 1) * 65536u);

        float c[4][4][4];
        #pragma unroll
        for (int mt = 0; mt < 4; mt++)
            #pragma unroll
            for (int nt = 0; nt < 4; nt++)
                #pragma unroll
                for (int k = 0; k < 4; k++) c[mt][nt][k] = 0.0f;

        #pragma unroll 4
        for (int ks = 0; ks < 16; ks++) {
            const uint32_t swA = (uint32_t)(((2u * ks + aSel) ^ (uint32_t)rlo) << 4);
            const uint32_t swB = (uint32_t)(((2u * ks + bSel) ^ (uint32_t)rlo) << 4);

            uint32_t af[4][4];
            #pragma unroll
            for (int mt = 0; mt < 4; mt++)
                ldsm4(af[mt][0], af[mt][1], af[mt][2], af[mt][3], baseA[mt] + swA);

            uint32_t bf[4][2];
            ldsm4(bf[0][0], bf[0][1], bf[1][0], bf[1][1], bbase + rowB[0] + swB);
            ldsm4(bf[2][0], bf[2][1], bf[3][0], bf[3][1], bbase + rowB[1] + swB);

            #pragma unroll
            for (int mt = 0; mt < 4; mt++)
                #pragma unroll
                for (int nt = 0; nt < 4; nt++)
                    mma16816(c[mt][nt], af[mt], bf[nt]);
        }

        // ---- fused epilogue: exp once, accumulate rowsums + per-tile colsums ----
        float cs[8];
        #pragma unroll
        for (int nt = 0; nt < 4; nt++) {
            float c0s = 0.0f, c1s = 0.0f;
            #pragma unroll
            for (int mt = 0; mt < 4; mt++) {
                float e0 = ex2f(fmaf(c[mt][nt][0], K2L, -K2L));
                float e1 = ex2f(fmaf(c[mt][nt][1], K2L, -K2L));
                float e2 = ex2f(fmaf(c[mt][nt][2], K2L, -K2L));
                float e3 = ex2f(fmaf(c[mt][nt][3], K2L, -K2L));
                rs[mt * 2 + 0] += e0 + e1;
                rs[mt * 2 + 1] += e2 + e3;
                c0s += e0 + e2;
                c1s += e1 + e3;
            }
            cs[nt * 2 + 0] = c0s;
            cs[nt * 2 + 1] = c1s;
        }
        if (t) {
            // reduce colsums over the 8 row-groups (lane bits 2,3,4), stash per m-half
            #pragma unroll
            for (int i = 0; i < 8; i++) {
                float v = cs[i];
                v += __shfl_xor_sync(0xffffffffu, v, 4);
                v += __shfl_xor_sync(0xffffffffu, v, 8);
                v += __shfl_xor_sync(0xffffffffu, v, 16);
                cs[i] = v;
            }
            if (lane < 4) {
                float* dstC = (wid < 4) ? stashC0 : stashC1;
                #pragma unroll
                for (int nt = 0; nt < 4; nt++) {
                    dstC[warp_n + nt * 8 + 2 * lane + 0] = cs[nt * 2 + 0];
                    dstC[warp_n + nt * 8 + 2 * lane + 1] = cs[nt * 2 + 1];
                }
            }
        }
        __syncthreads();  // all reads of B buffer + stash writes complete

        // prefetch B(t+2); always commit one group to keep wait-count invariant
        if (t >= 1 && t + 2 <= J)
            load_tile_async(sb + SM_B + (uint32_t)(t & 1) * 65536u,
                            gbase + (size_t)(((a + t + 2) & 127)) * 65536, tid);
        CP_COMMIT();

        // combine m-halves and write colsum slot for block b (unique writer)
        if (t && tid < 128) {
            const int b = (a + t) & 127;
            g_cs[((size_t)b * 64 + (t - 1)) * MT + tid] = stashC0[tid] + stashC1[tid];
        }
    }

    // ---- reduce local rowsums, write g_rs (unique writer per row) ----
    #pragma unroll
    for (int i = 0; i < 8; i++) {
        float v = rs[i];
        v += __shfl_xor_sync(0xffffffffu, v, 1);
        v += __shfl_xor_sync(0xffffffffu, v, 2);
        rs[i] = v;
    }
    float* stashR = reinterpret_cast<float*>(smem + SM_RSTASH);
    if ((lane & 3) == 0) {
        #pragma unroll
        for (int mt = 0; mt < 4; mt++)
            #pragma unroll
            for (int h = 0; h < 2; h++) {
                int row = warp_m + mt * 16 + h * 8 + (lane >> 2);
                stashR[(wid & 3) * 128 + row] = rs[mt * 2 + h];
            }
    }
    __syncthreads();
    if (wid < 4) {
        const int row = wid * 32 + lane;
        g_rs[m0 + row] = stashR[row] + stashR[128 + row] +
                         stashR[256 + row] + stashR[384 + row];
    }
}

// ---------------- Kernel 3: gather colsum slots, log, per-block partial ----------------
__global__ void __launch_bounds__(128) finalize1_kernel() {
    const int b   = blockIdx.x;
    const int tid = threadIdx.x;
    float tot = g_rs[b * MT + tid];
    const float* cs = g_cs + (size_t)b * 64 * MT + tid;
    #pragma unroll 8
    for (int s = 0; s < 64; s++) tot += cs[(size_t)s * MT];
    float loss = logf(tot) + (1.0f - g_diag[b * MT + tid]) * (1.0f / TEMP);
    #pragma unroll
    for (int o = 16; o; o >>= 1) loss += __shfl_xor_sync(0xffffffffu, loss, o);
    __shared__ float s4[4];
    if ((tid & 31) == 0) s4[tid >> 5] = loss;
    __syncthreads();
    if (tid == 0) g_partial[b] = (s4[0] + s4[1]) + (s4[2] + s4[3]);
}

// ---------------- Kernel 4: deterministic final reduce ----------------
__global__ void __launch_bounds__(128) finalize2_kernel(float* out) {
    const int tid = threadIdx.x;
    float v = g_partial[tid];
    #pragma unroll
    for (int o = 16; o; o >>= 1) v += __shfl_xor_sync(0xffffffffu, v, o);
    __shared__ float s4[4];
    if ((tid & 31) == 0) s4[tid >> 5] = v;
    __syncthreads();
    if (tid == 0) out[0] = ((s4[0] + s4[1]) + (s4[2] + s4[3])) * (1.0f / (float)NROWS);
}

// ---------------- launch ----------------
extern "C" void kernel_launch(void* const* d_in, const int* in_sizes, int n_in,
                              void* d_out, int out_size) {
    const float* emb = (const float*)d_in[0];
    float* out = (float*)d_out;
    (void)in_sizes; (void)n_in; (void)out_size;

    cudaFuncSetAttribute(contrastive_main,
                         cudaFuncAttributeMaxDynamicSharedMemorySize, SMEM_TOTAL);

    normalize_kernel<<<NROWS / 8, 256>>>(emb);
    contrastive_main<<<NCTA, 256, SMEM_TOTAL>>>();
    finalize1_kernel<<<NB, 128>>>();
    finalize2_kernel<<<1, 128>>>(out);
}